// round 7
// baseline (speedup 1.0000x reference)
#include <cuda_runtime.h>
#include <cuda_fp16.h>
#include <cstdint>
#include <math.h>

#define BATCH 2
#define CT 64      // thermal channels (= output channels)
#define CO 32      // optical channels (= V dim)
#define ED 64      // embed dim E
#define HI 32
#define WI 32
#define HO 96
#define WO 96
#define NQ (HO*WO)     // 9216
#define QB 128         // queries per CTA
#define KT 64          // keys per smem tile
#define NSPLIT 2       // key-dimension split
#define NT2 (NQ/KT/NSPLIT)   // 72 tiles per CTA
#define NQB (NQ/QB)    // 72 query blocks
#define QSCALE 0.180336880f   // (1/sqrt(64)) * log2(e): softmax becomes exp2(s)
#define PSTRIDE 36     // padded row: 32 num + den@32 + pad (144B, 16B aligned)

// scratch (allocation-free: __device__ globals)
__device__ __half g_qh[BATCH*NQ*ED];   // [b][n][e], pre-scaled by QSCALE
__device__ __half g_kh[BATCH*NQ*ED];   // [b][m][e]
__device__ __half g_vh[BATCH*NQ*CO];   // [b][m][o]
__device__ float  g_part[NSPLIT*BATCH*NQB*QB*PSTRIDE];  // split-K partials

// ---------------------------------------------------------------------------
// helpers
// ---------------------------------------------------------------------------
__device__ __forceinline__ uint32_t pack2(float a, float b) {
    __half2 h = __floats2half2_rn(a, b);
    return *(uint32_t*)&h;
}
__device__ __forceinline__ uint32_t h2ex2(uint32_t x) {
    uint32_t y; asm("ex2.approx.f16x2 %0, %1;" : "=r"(y) : "r"(x)); return y;
}
__device__ __forceinline__ void ldsm4(uint32_t* r, uint32_t addr) {
    asm volatile("ldmatrix.sync.aligned.m8n8.x4.shared.b16 {%0,%1,%2,%3}, [%4];"
        : "=r"(r[0]), "=r"(r[1]), "=r"(r[2]), "=r"(r[3]) : "r"(addr));
}
__device__ __forceinline__ void ldsm4t(uint32_t* r, uint32_t addr) {
    asm volatile("ldmatrix.sync.aligned.m8n8.x4.trans.shared.b16 {%0,%1,%2,%3}, [%4];"
        : "=r"(r[0]), "=r"(r[1]), "=r"(r[2]), "=r"(r[3]) : "r"(addr));
}
__device__ __forceinline__ void mma16816(float* c, const uint32_t* a, const uint32_t* b) {
    asm volatile("mma.sync.aligned.m16n8k16.row.col.f32.f16.f16.f32 "
        "{%0,%1,%2,%3}, {%4,%5,%6,%7}, {%8,%9}, {%0,%1,%2,%3};"
        : "+f"(c[0]), "+f"(c[1]), "+f"(c[2]), "+f"(c[3])
        : "r"(a[0]), "r"(a[1]), "r"(a[2]), "r"(a[3]), "r"(b[0]), "r"(b[1]));
}
__device__ __forceinline__ void mma16816h(uint32_t* c, const uint32_t* a, const uint32_t* b) {
    asm volatile("mma.sync.aligned.m16n8k16.row.col.f16.f16.f16.f16 "
        "{%0,%1}, {%2,%3,%4,%5}, {%6,%7}, {%0,%1};"
        : "+r"(c[0]), "+r"(c[1])
        : "r"(a[0]), "r"(a[1]), "r"(a[2]), "r"(a[3]), "r"(b[0]), "r"(b[1]));
}
__device__ __forceinline__ void cpasync16(uint32_t dst, const void* src) {
    asm volatile("cp.async.cg.shared.global [%0], [%1], 16;"
        :: "r"(dst), "l"(__cvta_generic_to_global(src)));
}

// ---------------------------------------------------------------------------
// Kernel 1 (merged projections): grid.y selects work group
//   y 0..3 : Q  (16 e-outputs per group)   y 4..7 : K    y 8..9 : V
// Q branch processes input channels in two halves of 32 to cut register use.
// ---------------------------------------------------------------------------
__global__ __launch_bounds__(128) void proj_kernel(
    const float* __restrict__ xt, const float* __restrict__ xo,
    const float* __restrict__ qw, const float* __restrict__ qb,
    const float* __restrict__ kw, const float* __restrict__ kb,
    const float* __restrict__ vw, const float* __restrict__ vb)
{
    __shared__ float ws[16*CT];
    __shared__ float bs[16];
    const int tid = threadIdx.x;
    const int grp = blockIdx.y;
    const int idx = blockIdx.x*128 + tid;
    const int b = idx / NQ;

    if (grp < 4) {
        int eb = grp * 16;
        for (int i = tid; i < 16*CT; i += 128) ws[i] = qw[eb*CT + i] * QSCALE;
        if (tid < 16) bs[tid] = qb[eb + tid] * QSCALE;
        __syncthreads();

        int n = idx % NQ;
        int y = n / WO, x = n % WO;
        float sy = (y + 0.5f) * (1.0f/3.0f) - 0.5f;
        float sx = (x + 0.5f) * (1.0f/3.0f) - 0.5f;
        float fy0 = floorf(sy), fx0 = floorf(sx);
        float fy = sy - fy0, fx = sx - fx0;
        int y0 = (int)fy0, x0 = (int)fx0;
        int y0c = max(y0, 0), y1c = min(y0+1, HI-1);
        int x0c = max(x0, 0), x1c = min(x0+1, WI-1);
        float w00 = (1.f-fy)*(1.f-fx), w01 = (1.f-fy)*fx;
        float w10 = fy*(1.f-fx),       w11 = fy*fx;

        float s[16];
        #pragma unroll
        for (int j = 0; j < 16; j++) s[j] = bs[j];

        const float* tb = xt + b*CT*HI*WI;
        #pragma unroll
        for (int half = 0; half < 2; half++) {
            float xv[32];
            #pragma unroll
            for (int cc = 0; cc < 32; cc++) {
                const float* p = tb + (half*32 + cc)*HI*WI;
                xv[cc] = w00*p[y0c*WI+x0c] + w01*p[y0c*WI+x1c]
                       + w10*p[y1c*WI+x0c] + w11*p[y1c*WI+x1c];
            }
            #pragma unroll
            for (int j = 0; j < 16; j++) {
                float acc = s[j];
                const float4* w4 = (const float4*)(ws + j*CT + half*32);
                #pragma unroll
                for (int c4 = 0; c4 < 8; c4++) {
                    float4 w = w4[c4];
                    acc = fmaf(w.x, xv[4*c4+0], acc);
                    acc = fmaf(w.y, xv[4*c4+1], acc);
                    acc = fmaf(w.z, xv[4*c4+2], acc);
                    acc = fmaf(w.w, xv[4*c4+3], acc);
                }
                s[j] = acc;
            }
        }
        uint4* dst = (uint4*)(g_qh + (size_t)idx*ED + eb);
        #pragma unroll
        for (int h = 0; h < 2; h++) {
            uint4 u;
            u.x = pack2(s[8*h+0], s[8*h+1]); u.y = pack2(s[8*h+2], s[8*h+3]);
            u.z = pack2(s[8*h+4], s[8*h+5]); u.w = pack2(s[8*h+6], s[8*h+7]);
            dst[h] = u;
        }
    } else {
        bool isv = grp >= 8;
        int ob = (isv ? (grp-8) : (grp-4)) * 16;
        const float* W  = isv ? vw : kw;
        const float* Bv = isv ? vb : kb;
        for (int i = tid; i < 16*CO; i += 128) ws[i] = W[ob*CO + i];
        if (tid < 16) bs[tid] = Bv[ob + tid];
        __syncthreads();

        int m = idx % NQ;
        float xv[CO];
        const float* p = xo + (size_t)b*CO*NQ + m;
        #pragma unroll
        for (int c = 0; c < CO; c++) xv[c] = p[(size_t)c*NQ];

        float s[16];
        #pragma unroll
        for (int j = 0; j < 16; j++) {
            float acc = bs[j];
            const float4* w4 = (const float4*)(ws + j*CO);
            #pragma unroll
            for (int c4 = 0; c4 < CO/4; c4++) {
                float4 w = w4[c4];
                acc = fmaf(w.x, xv[4*c4+0], acc);
                acc = fmaf(w.y, xv[4*c4+1], acc);
                acc = fmaf(w.z, xv[4*c4+2], acc);
                acc = fmaf(w.w, xv[4*c4+3], acc);
            }
            s[j] = acc;
        }
        __half* dst = (isv ? g_vh + (size_t)idx*CO : g_kh + (size_t)idx*ED) + ob;
        uint4* d4 = (uint4*)dst;
        #pragma unroll
        for (int h = 0; h < 2; h++) {
            uint4 u;
            u.x = pack2(s[8*h+0], s[8*h+1]); u.y = pack2(s[8*h+2], s[8*h+3]);
            u.z = pack2(s[8*h+4], s[8*h+5]); u.w = pack2(s[8*h+6], s[8*h+7]);
            d4[h] = u;
        }
    }
}

// ---------------------------------------------------------------------------
// Kernel 2: split-K flash attention (mma.sync). den on the fma/alu pipes via
// EXACT fp32 sums of individually-converted f16 P values (no f16 accumulation)
// -- numerically equivalent to the ones-B MMA, frees 4 tensor MMAs/warp-tile.
// grid = (72 qblocks, BATCH, NSPLIT); 2 CTAs/SM -> 4 warps/SMSP.
// ---------------------------------------------------------------------------
__global__ __launch_bounds__(256, 2) void attn_kernel()
{
    __shared__ __align__(16) char sm[47104];
    float* osm = (float*)sm;                 // epilogue overlay [128][36]

    const int tid = threadIdx.x;
    const int l = tid & 31, w = tid >> 5;
    const int b = blockIdx.y;
    const int z = blockIdx.z;

    uint32_t smb  = (uint32_t)__cvta_generic_to_shared(sm);
    uint32_t qs_b = smb;
    uint32_t ks_b = smb + 18432;
    uint32_t vs_b = smb + 36864;

    // ---- stage Q tile to smem (rows of 72 halves = 144B) ----
    {
        const uint4* qsrc = (const uint4*)(g_qh + ((size_t)b*NQ + blockIdx.x*QB)*ED);
        #pragma unroll
        for (int i = 0; i < 4; i++) {
            int c = tid + i*256;
            int row = c >> 3, c8 = c & 7;
            *(uint4*)(sm + row*144 + c8*16) = qsrc[row*8 + c8];
        }
    }
    __syncthreads();

    uint32_t qa[4][4];
    {
        int row = 16*w + (l & 15);
        int colh = l >> 4;
        #pragma unroll
        for (int kk = 0; kk < 4; kk++)
            ldsm4(qa[kk], qs_b + row*144 + (16*kk + 8*colh)*2);
    }

    const __half* kg = g_kh + (size_t)b*NQ*ED + (size_t)z*NT2*KT*ED;
    const __half* vg = g_vh + (size_t)b*NQ*CO + (size_t)z*NT2*KT*CO;

    auto load_tile = [&](int t, int buf) {
        #pragma unroll
        for (int i = 0; i < 2; i++) {
            int c = tid + i*256;
            int row = c >> 3, c8 = c & 7;
            cpasync16(ks_b + buf*9216 + row*144 + c8*16,
                      kg + (size_t)(t*KT + row)*ED + c8*8);
        }
        {
            int row = tid >> 2, c4 = tid & 3;
            cpasync16(vs_b + buf*5120 + row*80 + c4*16,
                      vg + (size_t)(t*KT + row)*CO + c4*8);
        }
        asm volatile("cp.async.commit_group;" ::);
    };

    const uint32_t k_lane = (uint32_t)((8*(l >> 4) + (l & 7))*144 + ((l & 15) >> 3)*16);
    const int vqd = l >> 3;
    const uint32_t v_lane = (uint32_t)(((vqd & 1)*8 + (l & 7))*80 + (vqd >> 1)*16);

    float oacc[4][4];
    #pragma unroll
    for (int ot = 0; ot < 4; ot++)
        #pragma unroll
        for (int r = 0; r < 4; r++) oacc[ot][r] = 0.f;
    float den0 = 0.f, den1 = 0.f;

    load_tile(0, 0);

    for (int t = 0; t < NT2; t++) {
        int buf = t & 1;
        if (t + 1 < NT2) {
            load_tile(t + 1, buf ^ 1);
            asm volatile("cp.async.wait_group 1;" ::);
        } else {
            asm volatile("cp.async.wait_group 0;" ::);
        }
        __syncthreads();

        // S = Q K^T in f16 accumulators
        uint32_t sc[8][2];
        #pragma unroll
        for (int j = 0; j < 8; j++) { sc[j][0] = 0u; sc[j][1] = 0u; }

        uint32_t kbase = ks_b + buf*9216 + k_lane;
        #pragma unroll
        for (int kk = 0; kk < 4; kk++) {
            uint32_t kb[16];
            #pragma unroll
            for (int j2 = 0; j2 < 4; j2++)
                ldsm4(&kb[4*j2], kbase + j2*2304 + kk*32);
            #pragma unroll
            for (int j = 0; j < 8; j++)
                mma16816h(sc[j], qa[kk], &kb[2*j]);
        }

        // P = exp2(S); f16 C-frag layout == A-frag layout
        uint32_t pa[4][4];
        #pragma unroll
        for (int kk2 = 0; kk2 < 4; kk2++) {
            pa[kk2][0] = h2ex2(sc[2*kk2][0]);
            pa[kk2][1] = h2ex2(sc[2*kk2][1]);
            pa[kk2][2] = h2ex2(sc[2*kk2+1][0]);
            pa[kk2][3] = h2ex2(sc[2*kk2+1][1]);
        }

        // den: exact fp32 sums of individually-converted f16 P values
        // (pa[*][0], pa[*][2] belong to row r0; pa[*][1], pa[*][3] to row r1)
        #pragma unroll
        for (int kk2 = 0; kk2 < 4; kk2++) {
            float2 f;
            f = __half22float2(*(__half2*)&pa[kk2][0]); den0 += f.x; den0 += f.y;
            f = __half22float2(*(__half2*)&pa[kk2][2]); den0 += f.x; den0 += f.y;
            f = __half22float2(*(__half2*)&pa[kk2][1]); den1 += f.x; den1 += f.y;
            f = __half22float2(*(__half2*)&pa[kk2][3]); den1 += f.x; den1 += f.y;
        }

        // O += P V
        uint32_t vbase = vs_b + buf*5120 + v_lane;
        #pragma unroll
        for (int kk2 = 0; kk2 < 4; kk2++) {
            uint32_t vb[8];
            ldsm4t(&vb[0], vbase + kk2*1280);
            ldsm4t(&vb[4], vbase + kk2*1280 + 32);
            #pragma unroll
            for (int ot = 0; ot < 4; ot++)
                mma16816(oacc[ot], pa[kk2], &vb[2*ot]);
        }
        __syncthreads();
    }

    // quad-reduce den (each thread held 16 of 64 columns per row)
    den0 += __shfl_xor_sync(0xffffffffu, den0, 1);
    den0 += __shfl_xor_sync(0xffffffffu, den0, 2);
    den1 += __shfl_xor_sync(0xffffffffu, den1, 1);
    den1 += __shfl_xor_sync(0xffffffffu, den1, 2);

    // ---- write unnormalized partials (num[32] + den) via smem staging ----
    {
        int g = l >> 2, tig = l & 3;
        int r0 = 16*w + g, r1 = r0 + 8;
        #pragma unroll
        for (int ot = 0; ot < 4; ot++) {
            osm[r0*PSTRIDE + 8*ot + 2*tig    ] = oacc[ot][0];
            osm[r0*PSTRIDE + 8*ot + 2*tig + 1] = oacc[ot][1];
            osm[r1*PSTRIDE + 8*ot + 2*tig    ] = oacc[ot][2];
            osm[r1*PSTRIDE + 8*ot + 2*tig + 1] = oacc[ot][3];
        }
        if (tig == 0) {
            osm[r0*PSTRIDE + 32] = den0;
            osm[r1*PSTRIDE + 32] = den1;
        }
    }
    __syncthreads();
    {
        float* dst = g_part + (size_t)((z*BATCH + b)*NQB + blockIdx.x) * (QB*PSTRIDE);
        #pragma unroll
        for (int i = 0; i < (QB*PSTRIDE)/256; i++)
            dst[tid + i*256] = osm[tid + i*256];
    }
}

// ---------------------------------------------------------------------------
// Kernel 3: combine split-K partials, normalize, fused conv + BN + ReLU
// grid = (144, 2): y splits the CT dimension in halves of 32
// ---------------------------------------------------------------------------
__global__ __launch_bounds__(128) void reduce_kernel(
    const float* __restrict__ ow,
    const float* __restrict__ gam, const float* __restrict__ bet,
    const float* __restrict__ mu,  const float* __restrict__ var,
    float* __restrict__ out)
{
    __shared__ float wsm[32*CO];
    __shared__ float bna[32], bnb[32];
    const int tid = threadIdx.x;
    const int r = blockIdx.x;            // b*NQB + qblock
    const int ch = blockIdx.y;           // ct half
    const int b = r / NQB;
    const int qbase = (r % NQB) * QB;
    const int ctb = ch * 32;

    for (int i = tid; i < 32*CO; i += 128) wsm[i] = ow[ctb*CO + i];
    if (tid < 32) {
        int ct = ctb + tid;
        float a = gam[ct] * rsqrtf(var[ct] + 1e-5f);
        bna[tid] = a;
        bnb[tid] = bet[ct] - mu[ct]*a;
    }
    __syncthreads();

    const float* p0 = g_part + (size_t)r * (QB*PSTRIDE) + tid*PSTRIDE;
    const float* p1 = p0 + (size_t)BATCH*NQB*QB*PSTRIDE;

    float den = p0[32] + p1[32];
    float inv = 1.0f / den;
    float a[CO];
    const float4* q0 = (const float4*)p0;
    const float4* q1 = (const float4*)p1;
    #pragma unroll
    for (int o4 = 0; o4 < CO/4; o4++) {
        float4 u = q0[o4], v = q1[o4];
        a[4*o4+0] = (u.x + v.x) * inv;
        a[4*o4+1] = (u.y + v.y) * inv;
        a[4*o4+2] = (u.z + v.z) * inv;
        a[4*o4+3] = (u.w + v.w) * inv;
    }

    float* op = out + (size_t)b*CT*NQ + (size_t)ctb*NQ + qbase + tid;
    #pragma unroll 4
    for (int ct = 0; ct < 32; ct++) {
        float g = 0.f;
        const float4* w4 = (const float4*)(wsm + ct*CO);
        #pragma unroll
        for (int o4 = 0; o4 < CO/4; o4++) {
            float4 wv = w4[o4];
            g = fmaf(wv.x, a[4*o4+0], g);
            g = fmaf(wv.y, a[4*o4+1], g);
            g = fmaf(wv.z, a[4*o4+2], g);
            g = fmaf(wv.w, a[4*o4+3], g);
        }
        g = fmaf(g, bna[ct], bnb[ct]);
        op[(size_t)ct*NQ] = fmaxf(g, 0.f);
    }
}

// ---------------------------------------------------------------------------
extern "C" void kernel_launch(void* const* d_in, const int* in_sizes, int n_in,
                              void* d_out, int out_size)
{
    const float* xt  = (const float*)d_in[0];
    const float* xo  = (const float*)d_in[1];
    const float* qw  = (const float*)d_in[2];
    const float* qb  = (const float*)d_in[3];
    const float* kw  = (const float*)d_in[4];
    const float* kb  = (const float*)d_in[5];
    const float* vw  = (const float*)d_in[6];
    const float* vb  = (const float*)d_in[7];
    const float* ow  = (const float*)d_in[8];
    const float* gam = (const float*)d_in[9];
    const float* bet = (const float*)d_in[10];
    const float* mu  = (const float*)d_in[11];
    const float* var = (const float*)d_in[12];
    float* out = (float*)d_out;

    dim3 gp((BATCH*NQ)/128, 10);
    proj_kernel<<<gp, 128>>>(xt, xo, qw, qb, kw, kb, vw, vb);
    dim3 ga(NQB, BATCH, NSPLIT);
    attn_kernel<<<ga, 256>>>();
    dim3 gr(BATCH*NQB, 2);
    reduce_kernel<<<gr, 128>>>(ow, gam, bet, mu, var, out);
}

// round 8
// speedup vs baseline: 1.0361x; 1.0361x over previous
#include <cuda_runtime.h>
#include <cuda_fp16.h>
#include <cstdint>
#include <math.h>

#define BATCH 2
#define CT 64      // thermal channels (= output channels)
#define CO 32      // optical channels (= V dim)
#define ED 64      // embed dim E
#define HI 32
#define WI 32
#define HO 96
#define WO 96
#define NQ (HO*WO)     // 9216
#define QB 128         // queries per CTA
#define KT 64          // keys per smem tile
#define NSPLIT 2       // key-dimension split
#define NT2 (NQ/KT/NSPLIT)   // 72 tiles per CTA
#define NQB (NQ/QB)    // 72 query blocks
#define QSCALE 0.180336880f   // (1/sqrt(64)) * log2(e): softmax becomes exp2(s)
#define ONES2 0x3C003C00u     // f16x2 {1.0, 1.0}
#define PSTRIDE 36     // padded row: 32 num + den@32 + pad (144B, 16B aligned)
#define NBUF 4         // K/V smem ring depth

// dynamic smem layout (75776 B total)
#define SM_Q   0                      // [128][144B]
#define SM_K   18432                  // 4 x [64 rows][144B] (128B data)
#define SM_V   55296                  // 4 x [64 rows][80B]
#define SM_TOTAL 75776
// epilogue overlays
#define SM_OSM 0                      // [128][36] f32
#define SM_WSM 18432                  // [64][32] f32
#define SM_BNA 26624
#define SM_BNB 26880

// scratch (allocation-free: __device__ globals)
__device__ __half g_qh[BATCH*NQ*ED];   // [b][n][e], pre-scaled by QSCALE
__device__ __half g_kh[BATCH*NQ*ED];   // [b][m][e]
__device__ __half g_vh[BATCH*NQ*CO];   // [b][m][o]
__device__ float  g_part[NSPLIT*BATCH*NQB*QB*PSTRIDE];  // split-K partials
__device__ int    g_sync[BATCH*NQB];   // per-qblock arrival counters (reset each launch)

// ---------------------------------------------------------------------------
// helpers
// ---------------------------------------------------------------------------
__device__ __forceinline__ uint32_t pack2(float a, float b) {
    __half2 h = __floats2half2_rn(a, b);
    return *(uint32_t*)&h;
}
__device__ __forceinline__ uint32_t h2ex2(uint32_t x) {
    uint32_t y; asm("ex2.approx.f16x2 %0, %1;" : "=r"(y) : "r"(x)); return y;
}
__device__ __forceinline__ void ldsm4(uint32_t* r, uint32_t addr) {
    asm volatile("ldmatrix.sync.aligned.m8n8.x4.shared.b16 {%0,%1,%2,%3}, [%4];"
        : "=r"(r[0]), "=r"(r[1]), "=r"(r[2]), "=r"(r[3]) : "r"(addr));
}
__device__ __forceinline__ void ldsm4t(uint32_t* r, uint32_t addr) {
    asm volatile("ldmatrix.sync.aligned.m8n8.x4.trans.shared.b16 {%0,%1,%2,%3}, [%4];"
        : "=r"(r[0]), "=r"(r[1]), "=r"(r[2]), "=r"(r[3]) : "r"(addr));
}
__device__ __forceinline__ void mma16816(float* c, const uint32_t* a, const uint32_t* b) {
    asm volatile("mma.sync.aligned.m16n8k16.row.col.f32.f16.f16.f32 "
        "{%0,%1,%2,%3}, {%4,%5,%6,%7}, {%8,%9}, {%0,%1,%2,%3};"
        : "+f"(c[0]), "+f"(c[1]), "+f"(c[2]), "+f"(c[3])
        : "r"(a[0]), "r"(a[1]), "r"(a[2]), "r"(a[3]), "r"(b[0]), "r"(b[1]));
}
__device__ __forceinline__ void mma16816h(uint32_t* c, const uint32_t* a, const uint32_t* b) {
    asm volatile("mma.sync.aligned.m16n8k16.row.col.f16.f16.f16.f16 "
        "{%0,%1}, {%2,%3,%4,%5}, {%6,%7}, {%0,%1};"
        : "+r"(c[0]), "+r"(c[1])
        : "r"(a[0]), "r"(a[1]), "r"(a[2]), "r"(a[3]), "r"(b[0]), "r"(b[1]));
}
__device__ __forceinline__ void cpasync16(uint32_t dst, const void* src) {
    asm volatile("cp.async.cg.shared.global [%0], [%1], 16;"
        :: "r"(dst), "l"(__cvta_generic_to_global(src)));
}
__device__ __forceinline__ void cp_commit() { asm volatile("cp.async.commit_group;" ::); }
__device__ __forceinline__ void cp_waitg(int n) {
    if (n == 0) asm volatile("cp.async.wait_group 0;" ::: "memory");
    else if (n == 1) asm volatile("cp.async.wait_group 1;" ::: "memory");
    else asm volatile("cp.async.wait_group 2;" ::: "memory");
}

// ---------------------------------------------------------------------------
// Kernel 1 (merged projections): grid.y selects work group
//   y 0..3 : Q  (16 e-outputs per group)   y 4..7 : K    y 8..9 : V
// ---------------------------------------------------------------------------
__global__ __launch_bounds__(128) void proj_kernel(
    const float* __restrict__ xt, const float* __restrict__ xo,
    const float* __restrict__ qw, const float* __restrict__ qb,
    const float* __restrict__ kw, const float* __restrict__ kb,
    const float* __restrict__ vw, const float* __restrict__ vb)
{
    __shared__ float ws[16*CT];
    __shared__ float bs[16];
    const int tid = threadIdx.x;
    const int grp = blockIdx.y;
    const int idx = blockIdx.x*128 + tid;
    const int b = idx / NQ;

    if (grp < 4) {
        int eb = grp * 16;
        for (int i = tid; i < 16*CT; i += 128) ws[i] = qw[eb*CT + i] * QSCALE;
        if (tid < 16) bs[tid] = qb[eb + tid] * QSCALE;
        __syncthreads();

        int n = idx % NQ;
        int y = n / WO, x = n % WO;
        float sy = (y + 0.5f) * (1.0f/3.0f) - 0.5f;
        float sx = (x + 0.5f) * (1.0f/3.0f) - 0.5f;
        float fy0 = floorf(sy), fx0 = floorf(sx);
        float fy = sy - fy0, fx = sx - fx0;
        int y0 = (int)fy0, x0 = (int)fx0;
        int y0c = max(y0, 0), y1c = min(y0+1, HI-1);
        int x0c = max(x0, 0), x1c = min(x0+1, WI-1);
        float w00 = (1.f-fy)*(1.f-fx), w01 = (1.f-fy)*fx;
        float w10 = fy*(1.f-fx),       w11 = fy*fx;

        float xv[CT];
        const float* tb = xt + b*CT*HI*WI;
        #pragma unroll
        for (int c = 0; c < CT; c++) {
            const float* p = tb + c*HI*WI;
            xv[c] = w00*p[y0c*WI+x0c] + w01*p[y0c*WI+x1c]
                  + w10*p[y1c*WI+x0c] + w11*p[y1c*WI+x1c];
        }
        float s[16];
        #pragma unroll
        for (int j = 0; j < 16; j++) {
            float acc = bs[j];
            const float4* w4 = (const float4*)(ws + j*CT);
            #pragma unroll
            for (int c4 = 0; c4 < CT/4; c4++) {
                float4 w = w4[c4];
                acc = fmaf(w.x, xv[4*c4+0], acc);
                acc = fmaf(w.y, xv[4*c4+1], acc);
                acc = fmaf(w.z, xv[4*c4+2], acc);
                acc = fmaf(w.w, xv[4*c4+3], acc);
            }
            s[j] = acc;
        }
        uint4* dst = (uint4*)(g_qh + (size_t)idx*ED + eb);
        #pragma unroll
        for (int h = 0; h < 2; h++) {
            uint4 u;
            u.x = pack2(s[8*h+0], s[8*h+1]); u.y = pack2(s[8*h+2], s[8*h+3]);
            u.z = pack2(s[8*h+4], s[8*h+5]); u.w = pack2(s[8*h+6], s[8*h+7]);
            dst[h] = u;
        }
    } else {
        bool isv = grp >= 8;
        int ob = (isv ? (grp-8) : (grp-4)) * 16;
        const float* W  = isv ? vw : kw;
        const float* Bv = isv ? vb : kb;
        for (int i = tid; i < 16*CO; i += 128) ws[i] = W[ob*CO + i];
        if (tid < 16) bs[tid] = Bv[ob + tid];
        __syncthreads();

        int m = idx % NQ;
        float xv[CO];
        const float* p = xo + (size_t)b*CO*NQ + m;
        #pragma unroll
        for (int c = 0; c < CO; c++) xv[c] = p[(size_t)c*NQ];

        float s[16];
        #pragma unroll
        for (int j = 0; j < 16; j++) {
            float acc = bs[j];
            const float4* w4 = (const float4*)(ws + j*CO);
            #pragma unroll
            for (int c4 = 0; c4 < CO/4; c4++) {
                float4 w = w4[c4];
                acc = fmaf(w.x, xv[4*c4+0], acc);
                acc = fmaf(w.y, xv[4*c4+1], acc);
                acc = fmaf(w.z, xv[4*c4+2], acc);
                acc = fmaf(w.w, xv[4*c4+3], acc);
            }
            s[j] = acc;
        }
        __half* dst = (isv ? g_vh + (size_t)idx*CO : g_kh + (size_t)idx*ED) + ob;
        uint4* d4 = (uint4*)dst;
        #pragma unroll
        for (int h = 0; h < 2; h++) {
            uint4 u;
            u.x = pack2(s[8*h+0], s[8*h+1]); u.y = pack2(s[8*h+2], s[8*h+3]);
            u.z = pack2(s[8*h+4], s[8*h+5]); u.w = pack2(s[8*h+6], s[8*h+7]);
            d4[h] = u;
        }
    }
}

// ---------------------------------------------------------------------------
// Kernel 2: split-K flash attention + fused split-combine epilogue.
// 4-deep K/V smem ring, ONE __syncthreads per tile, 2-tiles-ahead prefetch.
// Intra-tile pipelining: S(h0) -> ex2(h0) -> S(h1) -> PV(h0) -> ex2(h1) -> PV(h1).
// den via ones-B MMA (exact fp32). Second CTA of each split pair does the
// combine + 1x1 conv + BN + ReLU (atomic counter handshake).
// ---------------------------------------------------------------------------
__global__ __launch_bounds__(256, 2) void attn_kernel(
    const float* __restrict__ ow,
    const float* __restrict__ gam, const float* __restrict__ bet,
    const float* __restrict__ mu,  const float* __restrict__ var,
    float* __restrict__ out)
{
    extern __shared__ __align__(16) char sm[];
    float* osm = (float*)(sm + SM_OSM);

    const int tid = threadIdx.x;
    const int l = tid & 31, w = tid >> 5;
    const int b = blockIdx.y;
    const int z = blockIdx.z;
    const int r = b*NQB + blockIdx.x;    // qblock id

    uint32_t smb  = (uint32_t)__cvta_generic_to_shared(sm);
    uint32_t qs_b = smb + SM_Q;
    uint32_t ks_b = smb + SM_K;
    uint32_t vs_b = smb + SM_V;

    // ---- stage Q tile to smem (rows of 72 halves = 144B) ----
    {
        const uint4* qsrc = (const uint4*)(g_qh + ((size_t)b*NQ + blockIdx.x*QB)*ED);
        #pragma unroll
        for (int i = 0; i < 4; i++) {
            int c = tid + i*256;
            int row = c >> 3, c8 = c & 7;
            *(uint4*)(sm + SM_Q + row*144 + c8*16) = qsrc[row*8 + c8];
        }
    }
    __syncthreads();

    uint32_t qa[4][4];
    {
        int row = 16*w + (l & 15);
        int colh = l >> 4;
        #pragma unroll
        for (int kk = 0; kk < 4; kk++)
            ldsm4(qa[kk], qs_b + row*144 + (16*kk + 8*colh)*2);
    }

    const __half* kg = g_kh + (size_t)b*NQ*ED + (size_t)z*NT2*KT*ED;
    const __half* vg = g_vh + (size_t)b*NQ*CO + (size_t)z*NT2*KT*CO;

    auto load_tile = [&](int t) {
        int buf = t & (NBUF-1);
        #pragma unroll
        for (int i = 0; i < 2; i++) {
            int c = tid + i*256;
            int row = c >> 3, c8 = c & 7;
            cpasync16(ks_b + buf*9216 + row*144 + c8*16,
                      kg + (size_t)(t*KT + row)*ED + c8*8);
        }
        {
            int row = tid >> 2, c4 = tid & 3;
            cpasync16(vs_b + buf*5120 + row*80 + c4*16,
                      vg + (size_t)(t*KT + row)*CO + c4*8);
        }
        cp_commit();
    };

    const uint32_t k_lane = (uint32_t)((8*(l >> 4) + (l & 7))*144 + ((l & 15) >> 3)*16);
    const int vqd = l >> 3;
    const uint32_t v_lane = (uint32_t)(((vqd & 1)*8 + (l & 7))*80 + (vqd >> 1)*16);

    float oacc[4][4];
    #pragma unroll
    for (int ot = 0; ot < 4; ot++)
        #pragma unroll
        for (int rr = 0; rr < 4; rr++) oacc[ot][rr] = 0.f;
    float dacc[4] = {0.f, 0.f, 0.f, 0.f};
    const uint32_t bones[2] = { ONES2, ONES2 };

    load_tile(0);
    load_tile(1);

    for (int t = 0; t < NT2; t++) {
        if (t + 2 < NT2) { load_tile(t + 2); cp_waitg(2); }
        else if (t + 1 < NT2) cp_waitg(1);
        else cp_waitg(0);
        __syncthreads();   // single barrier per tile (4-deep ring => no WAR)

        int buf = t & (NBUF-1);
        uint32_t kbase = ks_b + buf*9216 + k_lane;
        uint32_t vbase = vs_b + buf*5120 + v_lane;

        uint32_t sc[8][2];
        #pragma unroll
        for (int j = 0; j < 8; j++) { sc[j][0] = 0u; sc[j][1] = 0u; }

        // ---- S half 0 (keys 0..31 of tile: j = 0..3) ----
        #pragma unroll
        for (int kk = 0; kk < 4; kk++) {
            uint32_t kb[8];
            ldsm4(&kb[0], kbase + 0*2304 + kk*32);
            ldsm4(&kb[4], kbase + 1*2304 + kk*32);
            mma16816h(sc[0], qa[kk], &kb[0]);
            mma16816h(sc[1], qa[kk], &kb[2]);
            mma16816h(sc[2], qa[kk], &kb[4]);
            mma16816h(sc[3], qa[kk], &kb[6]);
        }
        // ex2 half 0
        uint32_t pa[4][4];
        #pragma unroll
        for (int kk2 = 0; kk2 < 2; kk2++) {
            pa[kk2][0] = h2ex2(sc[2*kk2][0]);
            pa[kk2][1] = h2ex2(sc[2*kk2][1]);
            pa[kk2][2] = h2ex2(sc[2*kk2+1][0]);
            pa[kk2][3] = h2ex2(sc[2*kk2+1][1]);
        }
        // ---- S half 1 (keys 32..63: j = 4..7) — fills tensor pipe during ex2 ----
        #pragma unroll
        for (int kk = 0; kk < 4; kk++) {
            uint32_t kb[8];
            ldsm4(&kb[0], kbase + 2*2304 + kk*32);
            ldsm4(&kb[4], kbase + 3*2304 + kk*32);
            mma16816h(sc[4], qa[kk], &kb[0]);
            mma16816h(sc[5], qa[kk], &kb[2]);
            mma16816h(sc[6], qa[kk], &kb[4]);
            mma16816h(sc[7], qa[kk], &kb[6]);
        }
        // ---- PV half 0 ----
        #pragma unroll
        for (int kk2 = 0; kk2 < 2; kk2++) {
            uint32_t vb[8];
            ldsm4t(&vb[0], vbase + kk2*1280);
            ldsm4t(&vb[4], vbase + kk2*1280 + 32);
            #pragma unroll
            for (int ot = 0; ot < 4; ot++)
                mma16816(oacc[ot], pa[kk2], &vb[2*ot]);
            mma16816(dacc, pa[kk2], bones);
        }
        // ex2 half 1
        #pragma unroll
        for (int kk2 = 2; kk2 < 4; kk2++) {
            pa[kk2][0] = h2ex2(sc[2*kk2][0]);
            pa[kk2][1] = h2ex2(sc[2*kk2][1]);
            pa[kk2][2] = h2ex2(sc[2*kk2+1][0]);
            pa[kk2][3] = h2ex2(sc[2*kk2+1][1]);
        }
        // ---- PV half 1 ----
        #pragma unroll
        for (int kk2 = 2; kk2 < 4; kk2++) {
            uint32_t vb[8];
            ldsm4t(&vb[0], vbase + kk2*1280);
            ldsm4t(&vb[4], vbase + kk2*1280 + 32);
            #pragma unroll
            for (int ot = 0; ot < 4; ot++)
                mma16816(oacc[ot], pa[kk2], &vb[2*ot]);
            mma16816(dacc, pa[kk2], bones);
        }
    }

    // ---- stage unnormalized partials (num[32] + den) into smem ----
    __syncthreads();   // all warps done with K/V smem before overlay reuse
    {
        int g = l >> 2, tig = l & 3;
        int r0 = 16*w + g, r1 = r0 + 8;
        #pragma unroll
        for (int ot = 0; ot < 4; ot++) {
            osm[r0*PSTRIDE + 8*ot + 2*tig    ] = oacc[ot][0];
            osm[r0*PSTRIDE + 8*ot + 2*tig + 1] = oacc[ot][1];
            osm[r1*PSTRIDE + 8*ot + 2*tig    ] = oacc[ot][2];
            osm[r1*PSTRIDE + 8*ot + 2*tig + 1] = oacc[ot][3];
        }
        if (tig == 0) {
            osm[r0*PSTRIDE + 32] = dacc[0];
            osm[r1*PSTRIDE + 32] = dacc[2];
        }
    }
    __syncthreads();

    // ---- publish partial, then handshake: second CTA of the pair combines ----
    {
        float* dst = g_part + (size_t)(z*BATCH*NQB + r) * (QB*PSTRIDE);
        #pragma unroll
        for (int i = 0; i < (QB*PSTRIDE)/256; i++)
            dst[tid + i*256] = osm[tid + i*256];
    }
    __threadfence();
    __syncthreads();

    __shared__ int s_flag;
    if (tid == 0) {
        int old = atomicAdd(&g_sync[r], 1);
        s_flag = old;
        if (old == 1) atomicExch(&g_sync[r], 0);   // reset for next graph replay
    }
    __syncthreads();
    if (s_flag == 0) return;                       // producer path done
    __threadfence();                               // acquire other CTA's partial

    // ---- consumer: combine both partials (fixed z order), conv+BN+ReLU ----
    float* wsm = (float*)(sm + SM_WSM);
    float* bna = (float*)(sm + SM_BNA);
    float* bnb = (float*)(sm + SM_BNB);
    for (int i = tid; i < CT*CO; i += 256) wsm[i] = ow[i];
    if (tid < CT) {
        float a = gam[tid] * rsqrtf(var[tid] + 1e-5f);
        bna[tid] = a;
        bnb[tid] = bet[tid] - mu[tid]*a;
    }
    __syncthreads();

    {
        int q = tid & 127, h = tid >> 7;
        const float* p0 = g_part + (size_t)r * (QB*PSTRIDE) + q*PSTRIDE;
        const float* p1 = p0 + (size_t)BATCH*NQB*QB*PSTRIDE;

        float den = __ldcg(p0 + 32) + __ldcg(p1 + 32);
        float inv = 1.0f / den;
        float a[CO];
        #pragma unroll
        for (int o4 = 0; o4 < CO/4; o4++) {
            float4 u = __ldcg((const float4*)p0 + o4);
            float4 v = __ldcg((const float4*)p1 + o4);
            a[4*o4+0] = (u.x + v.x) * inv;
            a[4*o4+1] = (u.y + v.y) * inv;
            a[4*o4+2] = (u.z + v.z) * inv;
            a[4*o4+3] = (u.w + v.w) * inv;
        }

        float* op = out + (size_t)b*CT*NQ + blockIdx.x*QB + q;
        #pragma unroll 4
        for (int cc = 0; cc < 32; cc++) {
            int ct = h*32 + cc;
            float g = 0.f;
            const float4* w4 = (const float4*)(wsm + ct*CO);
            #pragma unroll
            for (int o4 = 0; o4 < CO/4; o4++) {
                float4 wv = w4[o4];
                g = fmaf(wv.x, a[4*o4+0], g);
                g = fmaf(wv.y, a[4*o4+1], g);
                g = fmaf(wv.z, a[4*o4+2], g);
                g = fmaf(wv.w, a[4*o4+3], g);
            }
            g = fmaf(g, bna[ct], bnb[ct]);
            op[(size_t)ct*NQ] = fmaxf(g, 0.f);
        }
    }
}

// ---------------------------------------------------------------------------
extern "C" void kernel_launch(void* const* d_in, const int* in_sizes, int n_in,
                              void* d_out, int out_size)
{
    const float* xt  = (const float*)d_in[0];
    const float* xo  = (const float*)d_in[1];
    const float* qw  = (const float*)d_in[2];
    const float* qb  = (const float*)d_in[3];
    const float* kw  = (const float*)d_in[4];
    const float* kb  = (const float*)d_in[5];
    const float* vw  = (const float*)d_in[6];
    const float* vb  = (const float*)d_in[7];
    const float* ow  = (const float*)d_in[8];
    const float* gam = (const float*)d_in[9];
    const float* bet = (const float*)d_in[10];
    const float* mu  = (const float*)d_in[11];
    const float* var = (const float*)d_in[12];
    float* out = (float*)d_out;

    static int smem_set = 0;
    if (!smem_set) {
        cudaFuncSetAttribute(attn_kernel,
            cudaFuncAttributeMaxDynamicSharedMemorySize, SM_TOTAL);
        smem_set = 1;
    }

    dim3 gp((BATCH*NQ)/128, 10);
    proj_kernel<<<gp, 128>>>(xt, xo, qw, qb, kw, kb, vw, vb);
    dim3 ga(NQB, BATCH, NSPLIT);
    attn_kernel<<<ga, 256, SM_TOTAL>>>(ow, gam, bet, mu, var, out);
}

// round 9
// speedup vs baseline: 1.1168x; 1.0779x over previous
#include <cuda_runtime.h>
#include <cuda_fp16.h>
#include <cstdint>
#include <math.h>

#define BATCH 2
#define CT 64      // thermal channels (= output channels)
#define CO 32      // optical channels (= V dim)
#define ED 64      // embed dim E
#define HI 32
#define WI 32
#define HO 96
#define WO 96
#define NQ (HO*WO)     // 9216
#define QB 128         // queries per CTA
#define KT 64          // keys per smem tile
#define NSPLIT 2       // key-dimension split
#define NT2 (NQ/KT/NSPLIT)   // 72 tiles per CTA
#define NQB (NQ/QB)    // 72 query blocks
#define QSCALE 0.180336880f   // (1/sqrt(64)) * log2(e): softmax becomes exp2(s)
#define ONES2 0x3C003C00u     // f16x2 {1.0, 1.0}
#define PSTRIDE 36     // padded row: 32 num + den@32 + pad (144B, 16B aligned)
#define NBUF 4         // K/V smem ring depth

// dynamic smem layout (75776 B total)
#define SM_Q   0                      // [128][144B]
#define SM_K   18432                  // 4 x [64 rows][144B] (128B data)
#define SM_V   55296                  // 4 x [64 rows][80B]
#define SM_TOTAL 75776
// epilogue overlays
#define SM_OSM 0                      // [128][36] f32
#define SM_WSM 18432                  // [64][32] f32
#define SM_BNA 26624
#define SM_BNB 26880

// scratch (allocation-free: __device__ globals)
__device__ __half g_qh[BATCH*NQ*ED];   // [b][n][e], pre-scaled by QSCALE
__device__ __half g_kh[BATCH*NQ*ED];   // [b][m][e]
__device__ __half g_vh[BATCH*NQ*CO];   // [b][m][o]
__device__ float  g_part[NSPLIT*BATCH*NQB*QB*PSTRIDE];  // split-K partials
__device__ int    g_sync[BATCH*NQB];   // per-qblock arrival counters

// ---------------------------------------------------------------------------
// helpers
// ---------------------------------------------------------------------------
__device__ __forceinline__ uint32_t pack2(float a, float b) {
    __half2 h = __floats2half2_rn(a, b);
    return *(uint32_t*)&h;
}
__device__ __forceinline__ uint32_t h2ex2(uint32_t x) {
    uint32_t y; asm("ex2.approx.f16x2 %0, %1;" : "=r"(y) : "r"(x)); return y;
}
__device__ __forceinline__ void ldsm4(uint32_t* r, uint32_t addr) {
    asm volatile("ldmatrix.sync.aligned.m8n8.x4.shared.b16 {%0,%1,%2,%3}, [%4];"
        : "=r"(r[0]), "=r"(r[1]), "=r"(r[2]), "=r"(r[3]) : "r"(addr));
}
__device__ __forceinline__ void ldsm4t(uint32_t* r, uint32_t addr) {
    asm volatile("ldmatrix.sync.aligned.m8n8.x4.trans.shared.b16 {%0,%1,%2,%3}, [%4];"
        : "=r"(r[0]), "=r"(r[1]), "=r"(r[2]), "=r"(r[3]) : "r"(addr));
}
__device__ __forceinline__ void mma16816(float* c, const uint32_t* a, const uint32_t* b) {
    asm volatile("mma.sync.aligned.m16n8k16.row.col.f32.f16.f16.f32 "
        "{%0,%1,%2,%3}, {%4,%5,%6,%7}, {%8,%9}, {%0,%1,%2,%3};"
        : "+f"(c[0]), "+f"(c[1]), "+f"(c[2]), "+f"(c[3])
        : "r"(a[0]), "r"(a[1]), "r"(a[2]), "r"(a[3]), "r"(b[0]), "r"(b[1]));
}
__device__ __forceinline__ void mma16816h(uint32_t* c, const uint32_t* a, const uint32_t* b) {
    asm volatile("mma.sync.aligned.m16n8k16.row.col.f16.f16.f16.f16 "
        "{%0,%1}, {%2,%3,%4,%5}, {%6,%7}, {%0,%1};"
        : "+r"(c[0]), "+r"(c[1])
        : "r"(a[0]), "r"(a[1]), "r"(a[2]), "r"(a[3]), "r"(b[0]), "r"(b[1]));
}
__device__ __forceinline__ void cpasync16(uint32_t dst, const void* src) {
    asm volatile("cp.async.cg.shared.global [%0], [%1], 16;"
        :: "r"(dst), "l"(__cvta_generic_to_global(src)));
}
__device__ __forceinline__ void cp_commit() { asm volatile("cp.async.commit_group;" ::); }
__device__ __forceinline__ void cp_waitg(int n) {
    if (n == 0) asm volatile("cp.async.wait_group 0;" ::: "memory");
    else if (n == 1) asm volatile("cp.async.wait_group 1;" ::: "memory");
    else asm volatile("cp.async.wait_group 2;" ::: "memory");
}

// ---------------------------------------------------------------------------
// Kernel 1 (merged projections): grid.y selects work group
//   y 0..3 : Q  (16 e-outputs per group)   y 4..7 : K    y 8..9 : V
// ---------------------------------------------------------------------------
__global__ __launch_bounds__(128) void proj_kernel(
    const float* __restrict__ xt, const float* __restrict__ xo,
    const float* __restrict__ qw, const float* __restrict__ qb,
    const float* __restrict__ kw, const float* __restrict__ kb,
    const float* __restrict__ vw, const float* __restrict__ vb)
{
    __shared__ float ws[16*CT];
    __shared__ float bs[16];
    const int tid = threadIdx.x;
    const int grp = blockIdx.y;
    const int idx = blockIdx.x*128 + tid;
    const int b = idx / NQ;

    if (grp < 4) {
        int eb = grp * 16;
        for (int i = tid; i < 16*CT; i += 128) ws[i] = qw[eb*CT + i] * QSCALE;
        if (tid < 16) bs[tid] = qb[eb + tid] * QSCALE;
        __syncthreads();

        int n = idx % NQ;
        int y = n / WO, x = n % WO;
        float sy = (y + 0.5f) * (1.0f/3.0f) - 0.5f;
        float sx = (x + 0.5f) * (1.0f/3.0f) - 0.5f;
        float fy0 = floorf(sy), fx0 = floorf(sx);
        float fy = sy - fy0, fx = sx - fx0;
        int y0 = (int)fy0, x0 = (int)fx0;
        int y0c = max(y0, 0), y1c = min(y0+1, HI-1);
        int x0c = max(x0, 0), x1c = min(x0+1, WI-1);
        float w00 = (1.f-fy)*(1.f-fx), w01 = (1.f-fy)*fx;
        float w10 = fy*(1.f-fx),       w11 = fy*fx;

        float xv[CT];
        const float* tb = xt + b*CT*HI*WI;
        #pragma unroll
        for (int c = 0; c < CT; c++) {
            const float* p = tb + c*HI*WI;
            xv[c] = w00*p[y0c*WI+x0c] + w01*p[y0c*WI+x1c]
                  + w10*p[y1c*WI+x0c] + w11*p[y1c*WI+x1c];
        }
        float s[16];
        #pragma unroll
        for (int j = 0; j < 16; j++) {
            float acc = bs[j];
            const float4* w4 = (const float4*)(ws + j*CT);
            #pragma unroll
            for (int c4 = 0; c4 < CT/4; c4++) {
                float4 w = w4[c4];
                acc = fmaf(w.x, xv[4*c4+0], acc);
                acc = fmaf(w.y, xv[4*c4+1], acc);
                acc = fmaf(w.z, xv[4*c4+2], acc);
                acc = fmaf(w.w, xv[4*c4+3], acc);
            }
            s[j] = acc;
        }
        uint4* dst = (uint4*)(g_qh + (size_t)idx*ED + eb);
        #pragma unroll
        for (int h = 0; h < 2; h++) {
            uint4 u;
            u.x = pack2(s[8*h+0], s[8*h+1]); u.y = pack2(s[8*h+2], s[8*h+3]);
            u.z = pack2(s[8*h+4], s[8*h+5]); u.w = pack2(s[8*h+6], s[8*h+7]);
            dst[h] = u;
        }
    } else {
        bool isv = grp >= 8;
        int ob = (isv ? (grp-8) : (grp-4)) * 16;
        const float* W  = isv ? vw : kw;
        const float* Bv = isv ? vb : kb;
        for (int i = tid; i < 16*CO; i += 128) ws[i] = W[ob*CO + i];
        if (tid < 16) bs[tid] = Bv[ob + tid];
        __syncthreads();

        int m = idx % NQ;
        float xv[CO];
        const float* p = xo + (size_t)b*CO*NQ + m;
        #pragma unroll
        for (int c = 0; c < CO; c++) xv[c] = p[(size_t)c*NQ];

        float s[16];
        #pragma unroll
        for (int j = 0; j < 16; j++) {
            float acc = bs[j];
            const float4* w4 = (const float4*)(ws + j*CO);
            #pragma unroll
            for (int c4 = 0; c4 < CO/4; c4++) {
                float4 w = w4[c4];
                acc = fmaf(w.x, xv[4*c4+0], acc);
                acc = fmaf(w.y, xv[4*c4+1], acc);
                acc = fmaf(w.z, xv[4*c4+2], acc);
                acc = fmaf(w.w, xv[4*c4+3], acc);
            }
            s[j] = acc;
        }
        __half* dst = (isv ? g_vh + (size_t)idx*CO : g_kh + (size_t)idx*ED) + ob;
        uint4* d4 = (uint4*)dst;
        #pragma unroll
        for (int h = 0; h < 2; h++) {
            uint4 u;
            u.x = pack2(s[8*h+0], s[8*h+1]); u.y = pack2(s[8*h+2], s[8*h+3]);
            u.z = pack2(s[8*h+4], s[8*h+5]); u.w = pack2(s[8*h+6], s[8*h+7]);
            d4[h] = u;
        }
    }
}

// ---------------------------------------------------------------------------
// Kernel 2: split-K flash attention, M=32 per warp (4 warps, 128 threads).
// Every K/V fragment loaded once per warp feeds TWO row-halves -> smem ldsm
// traffic per SM halves vs M=16. den via ones-B MMA. Fused split-combine
// epilogue (atomic handshake). 4-deep ring, one barrier per tile.
// ---------------------------------------------------------------------------
__global__ __launch_bounds__(128, 2) void attn_kernel(
    const float* __restrict__ ow,
    const float* __restrict__ gam, const float* __restrict__ bet,
    const float* __restrict__ mu,  const float* __restrict__ var,
    float* __restrict__ out)
{
    extern __shared__ __align__(16) char sm[];
    float* osm = (float*)(sm + SM_OSM);

    const int tid = threadIdx.x;
    const int l = tid & 31, w = tid >> 5;   // 4 warps
    const int b = blockIdx.y;
    const int z = blockIdx.z;
    const int r = b*NQB + blockIdx.x;       // qblock id

    uint32_t smb  = (uint32_t)__cvta_generic_to_shared(sm);
    uint32_t qs_b = smb + SM_Q;
    uint32_t ks_b = smb + SM_K;
    uint32_t vs_b = smb + SM_V;

    // ---- stage Q tile to smem (rows of 72 halves = 144B) ----
    {
        const uint4* qsrc = (const uint4*)(g_qh + ((size_t)b*NQ + blockIdx.x*QB)*ED);
        #pragma unroll
        for (int i = 0; i < 8; i++) {
            int c = tid + i*128;
            int row = c >> 3, c8 = c & 7;
            *(uint4*)(sm + SM_Q + row*144 + c8*16) = qsrc[row*8 + c8];
        }
    }
    __syncthreads();

    // ---- Q fragments: 2 row-halves x 4 k-steps (warp w owns rows [32w,32w+32)) ----
    uint32_t qa[2][4][4];
    {
        int colh = l >> 4;
        #pragma unroll
        for (int h = 0; h < 2; h++) {
            int row = 32*w + 16*h + (l & 15);
            #pragma unroll
            for (int kk = 0; kk < 4; kk++)
                ldsm4(qa[h][kk], qs_b + row*144 + (16*kk + 8*colh)*2);
        }
    }

    const __half* kg = g_kh + (size_t)b*NQ*ED + (size_t)z*NT2*KT*ED;
    const __half* vg = g_vh + (size_t)b*NQ*CO + (size_t)z*NT2*KT*CO;

    auto load_tile = [&](int t) {
        int buf = t & (NBUF-1);
        #pragma unroll
        for (int i = 0; i < 4; i++) {
            int c = tid + i*128;
            int row = c >> 3, c8 = c & 7;
            cpasync16(ks_b + buf*9216 + row*144 + c8*16,
                      kg + (size_t)(t*KT + row)*ED + c8*8);
        }
        #pragma unroll
        for (int i = 0; i < 2; i++) {
            int c = tid + i*128;
            int row = c >> 2, c4 = c & 3;
            cpasync16(vs_b + buf*5120 + row*80 + c4*16,
                      vg + (size_t)(t*KT + row)*CO + c4*8);
        }
        cp_commit();
    };

    const uint32_t k_lane = (uint32_t)((8*(l >> 4) + (l & 7))*144 + ((l & 15) >> 3)*16);
    const int vqd = l >> 3;
    const uint32_t v_lane = (uint32_t)(((vqd & 1)*8 + (l & 7))*80 + (vqd >> 1)*16);

    float oacc[2][4][4];
    #pragma unroll
    for (int h = 0; h < 2; h++)
        #pragma unroll
        for (int ot = 0; ot < 4; ot++)
            #pragma unroll
            for (int rr = 0; rr < 4; rr++) oacc[h][ot][rr] = 0.f;
    float dacc[2][4] = {{0.f,0.f,0.f,0.f},{0.f,0.f,0.f,0.f}};
    const uint32_t bones[2] = { ONES2, ONES2 };

    load_tile(0);
    load_tile(1);

    for (int t = 0; t < NT2; t++) {
        if (t + 2 < NT2) { load_tile(t + 2); cp_waitg(2); }
        else if (t + 1 < NT2) cp_waitg(1);
        else cp_waitg(0);
        __syncthreads();

        int buf = t & (NBUF-1);
        uint32_t kbase = ks_b + buf*9216 + k_lane;
        uint32_t vbase = vs_b + buf*5120 + v_lane;

        // sc[h][j][2] : S f16 accumulators; overwritten in place by exp2 -> P
        uint32_t sc[2][8][2];
        #pragma unroll
        for (int h = 0; h < 2; h++)
            #pragma unroll
            for (int j = 0; j < 8; j++) { sc[h][j][0] = 0u; sc[h][j][1] = 0u; }

        // ---- S, keys 0..31 (j = 0..3): each kb fragment feeds both row-halves ----
        #pragma unroll
        for (int kk = 0; kk < 4; kk++) {
            uint32_t kb[8];
            ldsm4(&kb[0], kbase + 0*2304 + kk*32);
            ldsm4(&kb[4], kbase + 1*2304 + kk*32);
            #pragma unroll
            for (int j = 0; j < 4; j++) {
                mma16816h(sc[0][j], qa[0][kk], &kb[2*j]);
                mma16816h(sc[1][j], qa[1][kk], &kb[2*j]);
            }
        }
        // ex2 keys 0..31
        #pragma unroll
        for (int h = 0; h < 2; h++)
            #pragma unroll
            for (int j = 0; j < 4; j++) {
                sc[h][j][0] = h2ex2(sc[h][j][0]);
                sc[h][j][1] = h2ex2(sc[h][j][1]);
            }
        // ---- S, keys 32..63 (j = 4..7) — fills tensor pipe during ex2 above ----
        #pragma unroll
        for (int kk = 0; kk < 4; kk++) {
            uint32_t kb[8];
            ldsm4(&kb[0], kbase + 2*2304 + kk*32);
            ldsm4(&kb[4], kbase + 3*2304 + kk*32);
            #pragma unroll
            for (int j = 0; j < 4; j++) {
                mma16816h(sc[0][4+j], qa[0][kk], &kb[2*j]);
                mma16816h(sc[1][4+j], qa[1][kk], &kb[2*j]);
            }
        }
        // ---- PV, keys 0..31 (kk2 = 0,1): vb shared by both row-halves ----
        #pragma unroll
        for (int kk2 = 0; kk2 < 2; kk2++) {
            uint32_t vb[8];
            ldsm4t(&vb[0], vbase + kk2*1280);
            ldsm4t(&vb[4], vbase + kk2*1280 + 32);
            #pragma unroll
            for (int h = 0; h < 2; h++) {
                uint32_t paH[4] = { sc[h][2*kk2][0], sc[h][2*kk2][1],
                                    sc[h][2*kk2+1][0], sc[h][2*kk2+1][1] };
                #pragma unroll
                for (int ot = 0; ot < 4; ot++)
                    mma16816(oacc[h][ot], paH, &vb[2*ot]);
                mma16816(dacc[h], paH, bones);
            }
        }
        // ex2 keys 32..63
        #pragma unroll
        for (int h = 0; h < 2; h++)
            #pragma unroll
            for (int j = 4; j < 8; j++) {
                sc[h][j][0] = h2ex2(sc[h][j][0]);
                sc[h][j][1] = h2ex2(sc[h][j][1]);
            }
        // ---- PV, keys 32..63 (kk2 = 2,3) ----
        #pragma unroll
        for (int kk2 = 2; kk2 < 4; kk2++) {
            uint32_t vb[8];
            ldsm4t(&vb[0], vbase + kk2*1280);
            ldsm4t(&vb[4], vbase + kk2*1280 + 32);
            #pragma unroll
            for (int h = 0; h < 2; h++) {
                uint32_t paH[4] = { sc[h][2*kk2][0], sc[h][2*kk2][1],
                                    sc[h][2*kk2+1][0], sc[h][2*kk2+1][1] };
                #pragma unroll
                for (int ot = 0; ot < 4; ot++)
                    mma16816(oacc[h][ot], paH, &vb[2*ot]);
                mma16816(dacc[h], paH, bones);
            }
        }
    }

    // ---- stage unnormalized partials (num[32] + den) into smem ----
    __syncthreads();
    {
        int g = l >> 2, tig = l & 3;
        #pragma unroll
        for (int h = 0; h < 2; h++) {
            int r0 = 32*w + 16*h + g, r1 = r0 + 8;
            #pragma unroll
            for (int ot = 0; ot < 4; ot++) {
                osm[r0*PSTRIDE + 8*ot + 2*tig    ] = oacc[h][ot][0];
                osm[r0*PSTRIDE + 8*ot + 2*tig + 1] = oacc[h][ot][1];
                osm[r1*PSTRIDE + 8*ot + 2*tig    ] = oacc[h][ot][2];
                osm[r1*PSTRIDE + 8*ot + 2*tig + 1] = oacc[h][ot][3];
            }
            if (tig == 0) {
                osm[r0*PSTRIDE + 32] = dacc[h][0];
                osm[r1*PSTRIDE + 32] = dacc[h][2];
            }
        }
    }
    __syncthreads();

    // ---- publish partial; second CTA of the split pair combines ----
    {
        float* dst = g_part + (size_t)(z*BATCH*NQB + r) * (QB*PSTRIDE);
        #pragma unroll
        for (int i = 0; i < (QB*PSTRIDE)/128; i++)
            dst[tid + i*128] = osm[tid + i*128];
    }
    __threadfence();
    __syncthreads();

    __shared__ int s_flag;
    if (tid == 0) {
        int old = atomicAdd(&g_sync[r], 1);
        s_flag = old;
        if (old == 1) atomicExch(&g_sync[r], 0);   // reset for graph replay
    }
    __syncthreads();
    if (s_flag == 0) return;
    __threadfence();

    // ---- consumer: combine both partials, conv+BN+ReLU ----
    float* wsm = (float*)(sm + SM_WSM);
    float* bna = (float*)(sm + SM_BNA);
    float* bnb = (float*)(sm + SM_BNB);
    for (int i = tid; i < CT*CO; i += 128) wsm[i] = ow[i];
    if (tid < CT) {
        float a = gam[tid] * rsqrtf(var[tid] + 1e-5f);
        bna[tid] = a;
        bnb[tid] = bet[tid] - mu[tid]*a;
    }
    __syncthreads();

    {
        int q = tid;
        const float* p0 = g_part + (size_t)r * (QB*PSTRIDE) + q*PSTRIDE;
        const float* p1 = p0 + (size_t)BATCH*NQB*QB*PSTRIDE;

        float den = __ldcg(p0 + 32) + __ldcg(p1 + 32);
        float inv = 1.0f / den;
        float a[CO];
        #pragma unroll
        for (int o4 = 0; o4 < CO/4; o4++) {
            float4 u = __ldcg((const float4*)p0 + o4);
            float4 v = __ldcg((const float4*)p1 + o4);
            a[4*o4+0] = (u.x + v.x) * inv;
            a[4*o4+1] = (u.y + v.y) * inv;
            a[4*o4+2] = (u.z + v.z) * inv;
            a[4*o4+3] = (u.w + v.w) * inv;
        }

        float* op = out + (size_t)b*CT*NQ + blockIdx.x*QB + q;
        #pragma unroll 4
        for (int ct = 0; ct < CT; ct++) {
            float g = 0.f;
            const float4* w4 = (const float4*)(wsm + ct*CO);
            #pragma unroll
            for (int o4 = 0; o4 < CO/4; o4++) {
                float4 wv = w4[o4];
                g = fmaf(wv.x, a[4*o4+0], g);
                g = fmaf(wv.y, a[4*o4+1], g);
                g = fmaf(wv.z, a[4*o4+2], g);
                g = fmaf(wv.w, a[4*o4+3], g);
            }
            g = fmaf(g, bna[ct], bnb[ct]);
            op[(size_t)ct*NQ] = fmaxf(g, 0.f);
        }
    }
}

// ---------------------------------------------------------------------------
extern "C" void kernel_launch(void* const* d_in, const int* in_sizes, int n_in,
                              void* d_out, int out_size)
{
    const float* xt  = (const float*)d_in[0];
    const float* xo  = (const float*)d_in[1];
    const float* qw  = (const float*)d_in[2];
    const float* qb  = (const float*)d_in[3];
    const float* kw  = (const float*)d_in[4];
    const float* kb  = (const float*)d_in[5];
    const float* vw  = (const float*)d_in[6];
    const float* vb  = (const float*)d_in[7];
    const float* ow  = (const float*)d_in[8];
    const float* gam = (const float*)d_in[9];
    const float* bet = (const float*)d_in[10];
    const float* mu  = (const float*)d_in[11];
    const float* var = (const float*)d_in[12];
    float* out = (float*)d_out;

    static int smem_set = 0;
    if (!smem_set) {
        cudaFuncSetAttribute(attn_kernel,
            cudaFuncAttributeMaxDynamicSharedMemorySize, SM_TOTAL);
        smem_set = 1;
    }

    dim3 gp((BATCH*NQ)/128, 10);
    proj_kernel<<<gp, 128>>>(xt, xo, qw, qb, kw, kb, vw, vb);
    dim3 ga(NQB, BATCH, NSPLIT);
    attn_kernel<<<ga, 128, SM_TOTAL>>>(ow, gam, bet, mu, var, out);
}